// round 10
// baseline (speedup 1.0000x reference)
#include <cuda_runtime.h>

// Casual_Conv1D: 31 chained Conv1d(1,1,k=2) == one 32-tap FIR + scalar bias.
// R10 (= R9 resubmit after broker infra failure; kernel audited clean).
// R=8 (8192 warps: warp-parallelism was capped by R=16 at 6.9/SMSP),
// pad-every-8 smem (stride-9 lanes, conflict-free, immediate offsets),
// compose overlapped with LDG latency, separate sout (2 barriers),
// alignment-safe scalar readout (R8's STG.128 faulted: 16353 % 4 == 1).

#define B_    128
#define L_    16384
#define NL_   31
#define LOUT_ (L_ - NL_)          // 16353
#define R_    8
#define TPB_  128
#define TILE_ (R_ * TPB_)         // 1024
#define PADN_ 1190                // inputs 1056, phys max 1185
#define PADO_ 1152                // outputs 1024, phys max 1150

typedef unsigned long long u64;

__device__ __forceinline__ u64 pk2(float lo, float hi) {
    u64 r; asm("mov.b64 %0, {%1, %2};" : "=l"(r) : "f"(lo), "f"(hi)); return r;
}
__device__ __forceinline__ void unpk2(u64 v, float& lo, float& hi) {
    asm("mov.b64 {%0, %1}, %2;" : "=f"(lo), "=f"(hi) : "l"(v));
}
__device__ __forceinline__ void ffma2(u64& d, u64 a, u64 b) {
    asm("fma.rn.f32x2 %0, %1, %2, %0;" : "+l"(d) : "l"(a), "l"(b));
}

__global__ void __launch_bounds__(TPB_)
fir_kernel(const float* __restrict__ x, const float* __restrict__ W,
           const float* __restrict__ b, float* __restrict__ y) {
    __shared__ float sbuf[PADN_];     // input tile (pad every 8: phys=i+(i>>3))
    __shared__ float sout[PADO_];     // output staging
    __shared__ u64   sc2[33];         // 32 coef pairs {c,c}; bias pair at [32]

    const int tid   = threadIdx.x;
    const int row   = blockIdx.y;
    const int tile0 = blockIdx.x * TILE_;
    const float* xrow = x + (size_t)row * L_ + tile0;
    const bool last = (tile0 + TILE_ + NL_ > L_);   // last tile of each row

    // ---- issue all global loads first (latency overlaps compose) ----
    float4 v0 = *reinterpret_cast<const float4*>(xrow + tid * 4);
    float4 v1 = *reinterpret_cast<const float4*>(xrow + tid * 4 + 512);
    float4 ve;
    const bool edge = (tid >= 32 && tid < 40);
    if (edge)
        ve = last ? make_float4(0.f, 0.f, 0.f, 0.f)
                  : *reinterpret_cast<const float4*>(xrow + 1024 + (tid - 32) * 4);

    // ---- warp 0: compose 31 k=2 filters while its LDGs are in flight ----
    if (tid < 32) {
        float c = (tid == 0) ? W[0] : ((tid == 1) ? W[1] : 0.0f);
        float d = b[0];
        #pragma unroll
        for (int i = 1; i < NL_; ++i) {
            const float w0 = W[2 * i], w1 = W[2 * i + 1];
            float cp = __shfl_up_sync(0xFFFFFFFFu, c, 1);
            if (tid == 0) cp = 0.0f;
            c = w0 * c + w1 * cp;
            d = (w0 + w1) * d + b[i];
        }
        sc2[tid] = pk2(c, c);
        if (tid == 0) sc2[32] = pk2(d, d);
    }

    // ---- stage tile: phys(4*tid + 512j + t) = 4*tid + tid/2 + 576j + t ----
    {
        float* sp = sbuf + tid * 4 + (tid >> 1);
        sp[0] = v0.x; sp[1] = v0.y; sp[2] = v0.z; sp[3] = v0.w;
        sp[576] = v1.x; sp[577] = v1.y; sp[578] = v1.z; sp[579] = v1.w;
    }
    if (edge) {   // phys(1024 + 4e + t) = 1152 + 4e + e/2 + t
        const int e = tid - 32;
        float* sp = sbuf + 1152 + e * 4 + (e >> 1);
        sp[0] = ve.x; sp[1] = ve.y; sp[2] = ve.z; sp[3] = ve.w;
    }
    __syncthreads();                             // barrier #1

    // ---- rolling pair-ring FIR: 8 outputs/thread, fma.rn.f32x2 ----
    // o0 = 8*tid; phys(o0+m) = 9*tid + m + m/8  (stride-9: conflict-free)
    const float* sp = sbuf + tid * 9;
#define XM(m_) sp[(m_) + ((m_) >> 3)]

    u64 pv[8];
    float prev = XM(0);
    #pragma unroll
    for (int t = 0; t < 8; ++t) {
        float nx = XM(t + 1);
        pv[t] = pk2(prev, nx);
        prev = nx;
    }
    float tailv = prev;                          // == x[o0+8]

    u64 acc[4];
    const u64 bias2 = sc2[32];
    #pragma unroll
    for (int j = 0; j < 4; ++j) acc[j] = bias2;

    #pragma unroll
    for (int k = 0; k < 32; ++k) {
        const u64 c2 = sc2[k];                   // LDS.64 broadcast
        #pragma unroll
        for (int j2 = 0; j2 < 4; ++j2)
            ffma2(acc[j2], c2, pv[(k + 2 * j2) & 7]);
        if (k < 30) {                            // refill slot with pair t=k+8
            float nx = XM(k + 9);
            pv[k & 7] = pk2(tailv, nx);
            tailv = nx;
        }
    }
#undef XM

    // ---- stage outputs: phys(8*tid + j) = 9*tid + j (conflict-free) ----
    {
        float* so = sout + tid * 9;
        #pragma unroll
        for (int j2 = 0; j2 < 4; ++j2) {
            float lo, hi; unpk2(acc[j2], lo, hi);
            so[2 * j2]     = lo;
            so[2 * j2 + 1] = hi;
        }
    }
    __syncthreads();                             // barrier #2

    // ---- coalesced scalar readout: i = tid + 128j, phys = i + i/8 ----
    float* yrow = y + (size_t)row * LOUT_ + tile0 + tid;
    const float* sr = sout + tid + (tid >> 3);
    if (!last) {
        #pragma unroll
        for (int j = 0; j < R_; ++j)
            yrow[j * 128] = sr[j * 144];
    } else {
        const int nvalid = LOUT_ - tile0;        // 993
        #pragma unroll
        for (int j = 0; j < R_; ++j)
            if (tid + j * 128 < nvalid)
                yrow[j * 128] = sr[j * 144];
    }
}

// ---------------------------------------------------------------------------
extern "C" void kernel_launch(void* const* d_in, const int* in_sizes, int n_in,
                              void* d_out, int out_size) {
    const float* x = (const float*)d_in[0];   // (128, 1, 16384) f32
    const float* W = (const float*)d_in[1];   // (31, 2) f32
    const float* b = (const float*)d_in[2];   // (31,)  f32
    float* y = (float*)d_out;                 // (128, 1, 16353) f32

    dim3 grid(L_ / TILE_, B_);                // (16, 128) = 2048 blocks
    fir_kernel<<<grid, TPB_>>>(x, W, b, y);
}

// round 11
// speedup vs baseline: 1.1476x; 1.1476x over previous
#include <cuda_runtime.h>

// Casual_Conv1D: 31 chained Conv1d(1,1,k=2) == one 32-tap FIR + scalar bias.
// R11: best measured geometry (R=16, TPB=128 from R7) + R8 structural fixes:
// compose overlapped with in-flight LDGs, separate sout (2 barriers), scalar
// alignment-safe readout. f32x2 dropped: measured fma-pipe cycles identical
// to scalar FFMA (R2 vs R6) while adding pack ALU + u64 pressure. Scalar
// 16-float rolling ring, immediate-offset pad-16 smem addressing.

#define B_    128
#define L_    16384
#define NL_   31
#define LOUT_ (L_ - NL_)          // 16353
#define R_    16
#define TPB_  128
#define TILE_ (R_ * TPB_)         // 2048
#define PADN_ 2212                // inputs 2080, phys max 2208
#define PADO_ 2176                // outputs 2048, phys max 2174

__global__ void __launch_bounds__(TPB_)
fir_kernel(const float* __restrict__ x, const float* __restrict__ W,
           const float* __restrict__ b, float* __restrict__ y) {
    __shared__ float sbuf[PADN_];     // input tile, pad-16: phys = i + (i>>4)
    __shared__ float sout[PADO_];     // output staging
    __shared__ float sc[33];          // 32 coefficients + bias at [32]

    const int tid   = threadIdx.x;
    const int row   = blockIdx.y;
    const int tile0 = blockIdx.x * TILE_;
    const float* xrow = x + (size_t)row * L_ + tile0;
    const bool last = (tile0 + TILE_ + NL_ > L_);   // last tile of each row

    // ---- issue all global loads first (latency overlaps compose) ----
    float4 v[4];
    #pragma unroll
    for (int j = 0; j < 4; ++j)
        v[j] = *reinterpret_cast<const float4*>(xrow + tid * 4 + j * 512);
    float4 ve;
    const bool edge = (tid >= 32 && tid < 40);
    if (edge)
        ve = last ? make_float4(0.f, 0.f, 0.f, 0.f)
                  : *reinterpret_cast<const float4*>(xrow + 2048 + (tid - 32) * 4);

    // ---- warp 0: compose 31 k=2 filters while its LDGs are in flight ----
    if (tid < 32) {
        float c = (tid == 0) ? W[0] : ((tid == 1) ? W[1] : 0.0f);
        float d = b[0];
        #pragma unroll
        for (int i = 1; i < NL_; ++i) {
            const float w0 = W[2 * i], w1 = W[2 * i + 1];
            float cp = __shfl_up_sync(0xFFFFFFFFu, c, 1);
            if (tid == 0) cp = 0.0f;
            c = w0 * c + w1 * cp;
            d = (w0 + w1) * d + b[i];
        }
        sc[tid] = c;
        if (tid == 0) sc[32] = d;
    }

    // ---- stage tile: phys(4*tid + 512j + t) = 4*tid + tid/4 + 544j + t ----
    {
        float* sp = sbuf + tid * 4 + (tid >> 2);
        #pragma unroll
        for (int j = 0; j < 4; ++j) {
            sp[j * 544 + 0] = v[j].x;
            sp[j * 544 + 1] = v[j].y;
            sp[j * 544 + 2] = v[j].z;
            sp[j * 544 + 3] = v[j].w;
        }
    }
    if (edge) {   // phys(2048 + 4e + t) = 2176 + 4e + e/4 + t
        const int e = tid - 32;
        float* sp = sbuf + 2176 + e * 4 + (e >> 2);
        sp[0] = ve.x; sp[1] = ve.y; sp[2] = ve.z; sp[3] = ve.w;
    }
    __syncthreads();                             // barrier #1

    // ---- scalar rolling-ring FIR: 16 outputs/thread ----
    // o0 = 16*tid; phys(o0+m) = 17*tid + m + m/16 (stride-17: conflict-free)
    const float* sp = sbuf + tid * 17;
#define XM(m_) sp[(m_) + ((m_) >> 4)]

    float r[16];
    #pragma unroll
    for (int t = 0; t < 16; ++t) r[t] = XM(t);

    const float bias = sc[32];
    float acc[16];
    #pragma unroll
    for (int j = 0; j < 16; ++j) acc[j] = bias;

    #pragma unroll
    for (int k = 0; k < 32; ++k) {
        const float ck = sc[k];                  // LDS broadcast, imm offset
        #pragma unroll
        for (int j = 0; j < 16; ++j)
            acc[j] += ck * r[(k + j) & 15];      // compile-time after unroll
        if (k < 31)                              // refill slot with t = k+16
            r[k & 15] = XM(k + 16);
    }
#undef XM

    // ---- stage outputs: phys(16*tid + j) = 17*tid + j (conflict-free) ----
    {
        float* so = sout + tid * 17;
        #pragma unroll
        for (int j = 0; j < 16; ++j)
            so[j] = acc[j];
    }
    __syncthreads();                             // barrier #2

    // ---- coalesced scalar readout: i = tid + 128j, phys = i + i/16 ----
    float* yrow = y + (size_t)row * LOUT_ + tile0 + tid;
    const float* sr = sout + tid + (tid >> 4);
    if (!last) {
        #pragma unroll
        for (int j = 0; j < R_; ++j)
            yrow[j * 128] = sr[j * 136];
    } else {
        const int nvalid = LOUT_ - tile0;        // 2017
        #pragma unroll
        for (int j = 0; j < R_; ++j)
            if (tid + j * 128 < nvalid)
                yrow[j * 128] = sr[j * 136];
    }
}

// ---------------------------------------------------------------------------
extern "C" void kernel_launch(void* const* d_in, const int* in_sizes, int n_in,
                              void* d_out, int out_size) {
    const float* x = (const float*)d_in[0];   // (128, 1, 16384) f32
    const float* W = (const float*)d_in[1];   // (31, 2) f32
    const float* b = (const float*)d_in[2];   // (31,)  f32
    float* y = (float*)d_out;                 // (128, 1, 16353) f32

    dim3 grid(L_ / TILE_, B_);                // (8, 128) = 1024 blocks
    fir_kernel<<<grid, TPB_>>>(x, W, b, y);
}